// round 4
// baseline (speedup 1.0000x reference)
#include <cuda_runtime.h>

// 0: x [2,192,88,133] f32, 1: W_lin [133,24], 2: b_lin [24], 3: W_qkv [24,72],
// 4: b_qkv [72], 5: rpb [4,49,49], 6: W_proj [24,24], 7: b_proj [24]
// output: [2,192,88,24] f32

#define BB   2
#define HT   192
#define WD   88
#define FIN  133
#define CC   24
#define NH   4
#define DH   6
#define WIN  25
#define NPIX (BB*HT*WD)   // 33792
#define RPBW 49
#define TQ   6            // query rows per attn block
#define NTA  176          // attn threads: 44 cols x 4 heads
#define BROWS 35
#define BH   (BROWS*RPBW) // 1715
#define KW   56           // staged key columns per row (per j-half)

typedef unsigned long long ull;

// Scratch (device globals: allocation-free)
__device__ float g_q[NPIX*CC], g_k[NPIX*CC], g_v[NPIX*CC];     // layer-1 qkv, [bi][ch][col]
__device__ float g_q2[NPIX*CC], g_k2[NPIX*CC], g_v2[NPIX*CC];  // layer-2 qkv
__device__ float g_wc[CC*72], g_bc[72];                        // combined proj@qkv

// ---- packed f32x2 helpers (Blackwell) --------------------------------------
__device__ __forceinline__ ull pk2(float lo, float hi) {
    ull r; asm("mov.b64 %0, {%1,%2};" : "=l"(r) : "f"(lo), "f"(hi)); return r;
}
__device__ __forceinline__ ull bc2(float v) { return pk2(v, v); }
__device__ __forceinline__ void upk2(float& lo, float& hi, ull v) {
    asm("mov.b64 {%0,%1}, %2;" : "=f"(lo), "=f"(hi) : "l"(v));
}
__device__ __forceinline__ ull fma2(ull a, ull b, ull c) {
    ull d; asm("fma.rn.f32x2 %0, %1, %2, %3;" : "=l"(d) : "l"(a), "l"(b), "l"(c)); return d;
}
__device__ __forceinline__ ull add2(ull a, ull b) {
    ull d; asm("add.rn.f32x2 %0, %1, %2;" : "=l"(d) : "l"(a), "l"(b)); return d;
}

// ---------------------------------------------------------------------------
// Setup: Wcomb = W_proj @ W_qkv, bcomb = b_proj @ W_qkv + b_qkv (q-cols scaled)
// ---------------------------------------------------------------------------
__global__ void k_comb(const float* __restrict__ Wp, const float* __restrict__ bp,
                       const float* __restrict__ Wq, const float* __restrict__ bq) {
    int t = blockIdx.x * blockDim.x + threadIdx.x;
    const float QS = 0.40824829046386302f;
    if (t < CC*72) {
        int u = t / 72, cf = t % 72;
        float a = 0.f;
        #pragma unroll
        for (int w = 0; w < CC; ++w) a = fmaf(Wp[u*CC + w], Wq[w*72 + cf], a);
        if (cf < CC) a *= QS;
        g_wc[t] = a;
    }
    if (t < 72) {
        float a = bq[t];
        #pragma unroll
        for (int w = 0; w < CC; ++w) a = fmaf(bp[w], Wq[w*72 + t], a);
        if (t < CC) a *= QS;
        g_bc[t] = a;
    }
}

// ---------------------------------------------------------------------------
// Fused linear+ReLU+qkv: block = 44-pixel half row. Writes g_q/g_k/g_v d-major.
// ---------------------------------------------------------------------------
__global__ void __launch_bounds__(352) k_linqkv(const float* __restrict__ x,
                                                const float* __restrict__ Wl,
                                                const float* __restrict__ bl,
                                                const float* __restrict__ Wq,
                                                const float* __restrict__ bq) {
    __shared__ float sm[11872];
    float* xs = sm;               // 44*133 = 5852
    float* wl = sm + 5852;        // 133*24 = 3192
    float* hs = sm + 9044;        // 44*25  = 1100
    float* wq = sm + 10144;       // 24*72  = 1728

    int blk = blockIdx.x;
    int bi = blk >> 1, jb = (blk & 1) * 44;
    int tid = threadIdx.x;

    const float* xb = x + ((size_t)bi * WD + jb) * FIN;
    for (int idx = tid; idx < 44*FIN; idx += 352) xs[idx] = xb[idx];
    for (int idx = tid; idx < FIN*CC; idx += 352) wl[idx] = Wl[idx];
    for (int idx = tid; idx < CC*72; idx += 352) wq[idx] = Wq[idx];
    __syncthreads();

    int jl = tid % 44, cg = tid / 44;      // cg in [0,8): 3 channels each
    int c0 = cg * 3;
    float acc[3];
    #pragma unroll
    for (int i = 0; i < 3; ++i) acc[i] = bl[c0 + i];
    #pragma unroll 7
    for (int f = 0; f < FIN; ++f) {
        float xf = xs[jl*FIN + f];
        #pragma unroll
        for (int i = 0; i < 3; ++i) acc[i] = fmaf(xf, wl[f*CC + c0 + i], acc[i]);
    }
    #pragma unroll
    for (int i = 0; i < 3; ++i) hs[jl*25 + c0 + i] = fmaxf(acc[i], 0.f);
    __syncthreads();

    for (int o = tid; o < 44*72; o += 352) {
        int cf = o / 44, j2 = o - cf*44;
        float a = bq[cf];
        #pragma unroll
        for (int u = 0; u < CC; ++u) a = fmaf(hs[j2*25 + u], wq[u*72 + cf], a);
        if (cf < CC) a *= 0.40824829046386302f;
        int which = cf / CC, ch = cf % CC;
        float* dst = (which == 0) ? g_q : (which == 1) ? g_k : g_v;
        dst[((size_t)bi * CC + ch) * WD + jb + j2] = a;
    }
}

// ---------------------------------------------------------------------------
// Attention: block = (b, 6-row group, j-half). 176 threads = (44 j x 4 h).
// 6 queries/thread; packed f32x2 FMAs (query-pair lanes). Direct exp with
// center-score subtraction; invalid rows get a -60 shift (p ~ 1e-13).
// MODE 0: epilogue writes next layer's qkv via Wcomb. MODE 1: final proj.
// ---------------------------------------------------------------------------
template<int MODE>
__global__ void __launch_bounds__(NTA, 1) k_attn(
    const float* __restrict__ Q, const float* __restrict__ K,
    const float* __restrict__ V, const float* __restrict__ rpb,
    const float* __restrict__ W, const float* __restrict__ bvec,
    float* __restrict__ outp)
{
    __shared__ float smem[9548];
    float* bias_s = smem;           // 4*35*49 = 6860
    float* k_s = smem + 6860;       // 24*56 = 1344
    float* v_s = smem + 8204;       // 1344

    int idxb = blockIdx.x;          // 128 blocks
    int jh = idxb & 1, ig = (idxb >> 1) & 31, b = idxb >> 6;
    int i0 = ig * TQ, jb = jh * 44, col_base = jh * 32;
    int tid = threadIdx.x;
    int jl = tid % 44, h = tid / 44;
    int j = jb + jl, h6 = h * DH;

    int sii[TQ];
    #pragma unroll
    for (int t = 0; t < TQ; ++t) sii[t] = min(max(i0 + t - 12, 0), HT - WIN);
    int r_lo = sii[0], r_hi = sii[TQ-1] + 24;
    int nrows = r_hi - r_lo + 1;    // 25..30
    int base = r_lo - i0 + 19;

    int sjj = min(max(j - 12, 0), WD - WIN);
    int scol = sjj - col_base;      // [0,31]
    int bjcol = sjj - j + 24;

    for (int idx = tid; idx < NH*BH; idx += NTA) {
        int hh = idx / BH, rem = idx - hh*BH;
        int s = rem / RPBW, ccol = rem - s*RPBW;
        int src = min(max(base + s, 0), RPBW - 1);
        bias_s[idx] = rpb[hh*RPBW*RPBW + src*RPBW + ccol];
    }

    // q (packed per query-pair per d) + negated center scores
    float nscs[TQ];
    ull qvp[3][DH];
    {
        float qv[TQ][DH];
        #pragma unroll
        for (int t = 0; t < TQ; ++t) {
            const float* qb = Q + ((size_t)(b*HT + i0 + t) * CC + h6) * WD + j;
            const float* kc = K + ((size_t)(b*HT + i0 + t) * CC + h6) * WD + j;
            float s = 0.f;
            #pragma unroll
            for (int d = 0; d < DH; ++d) {
                qv[t][d] = qb[d*WD];
                s = fmaf(qv[t][d], kc[d*WD], s);
            }
            nscs[t] = -s;
        }
        #pragma unroll
        for (int p = 0; p < 3; ++p)
            #pragma unroll
            for (int d = 0; d < DH; ++d) qvp[p][d] = pk2(qv[2*p][d], qv[2*p+1][d]);
    }

    ull accp[3][DH], lp[3];
    #pragma unroll
    for (int p = 0; p < 3; ++p) {
        lp[p] = 0ULL;
        #pragma unroll
        for (int d = 0; d < DH; ++d) accp[p][d] = 0ULL;
    }

    // register prefetch of first K/V row slice
    float kr[8], vr[8];
    {
        size_t off = ((size_t)(b*HT + r_lo) * CC) * WD + col_base;
        #pragma unroll
        for (int u = 0; u < 8; ++u) {
            int idx = tid + u*NTA;
            if (idx < CC*KW) {
                int ch = idx / KW, c = idx - ch*KW;
                kr[u] = K[off + ch*WD + c];
                vr[u] = V[off + ch*WD + c];
            }
        }
    }

    for (int rr = 0; rr < nrows; ++rr) {
        int r = r_lo + rr;
        __syncthreads();
        #pragma unroll
        for (int u = 0; u < 8; ++u) {
            int idx = tid + u*NTA;
            if (idx < CC*KW) { k_s[idx] = kr[u]; v_s[idx] = vr[u]; }
        }
        __syncthreads();
        if (rr + 1 < nrows) {
            size_t off = ((size_t)(b*HT + r + 1) * CC) * WD + col_base;
            #pragma unroll
            for (int u = 0; u < 8; ++u) {
                int idx = tid + u*NTA;
                if (idx < CC*KW) {
                    int ch = idx / KW, c = idx - ch*KW;
                    kr[u] = K[off + ch*WD + c];
                    vr[u] = V[off + ch*WD + c];
                }
            }
        }

        ull nscr[3];
        #pragma unroll
        for (int p = 0; p < 3; ++p) {
            int t0 = 2*p, t1 = 2*p + 1;
            float a0 = nscs[t0] + ((r >= sii[t0] && r <= sii[t0] + 24) ? 0.f : -60.f);
            float a1 = nscs[t1] + ((r >= sii[t1] && r <= sii[t1] + 24) ? 0.f : -60.f);
            nscr[p] = pk2(a0, a1);
        }

        const float* kb = k_s + h6*KW + scol;
        const float* vb = v_s + h6*KW + scol;
        const float* brb = bias_s + h*BH + (rr + 5)*RPBW + bjcol;  // query t: brb - t*49

        #pragma unroll
        for (int c = 0; c < WIN; ++c) {
            ull kcb[DH], vcb[DH];
            #pragma unroll
            for (int d = 0; d < DH; ++d) {
                kcb[d] = bc2(kb[d*KW + c]);
                vcb[d] = bc2(vb[d*KW + c]);
            }
            #pragma unroll
            for (int p = 0; p < 3; ++p) {
                int t0 = 2*p;
                ull s = add2(pk2(brb[c - t0*RPBW], brb[c - (t0+1)*RPBW]), nscr[p]);
                #pragma unroll
                for (int d = 0; d < DH; ++d) s = fma2(qvp[p][d], kcb[d], s);
                float s0, s1; upk2(s0, s1, s);
                ull pp = pk2(__expf(s0), __expf(s1));
                lp[p] = add2(lp[p], pp);
                #pragma unroll
                for (int d = 0; d < DH; ++d) accp[p][d] = fma2(pp, vcb[d], accp[p][d]);
            }
        }
    }

    // ---- epilogue: normalize -> attn_s, then GEMM with W (Wcomb or Wproj) --
    __syncthreads();
    float* attn_s = smem;                    // 264*25 = 6600
    const int NOUT = (MODE == 0) ? 72 : 24;
    float* ws = smem + 6600;                 // <= 1728
    float* bs = smem + 6600 + 1728;          // <= 72

    #pragma unroll
    for (int p = 0; p < 3; ++p) {
        float l0, l1; upk2(l0, l1, lp[p]);
        float i0v = __fdividef(1.f, l0);
        float i1v = __fdividef(1.f, l1);
        #pragma unroll
        for (int d = 0; d < DH; ++d) {
            float a0, a1; upk2(a0, a1, accp[p][d]);
            attn_s[((2*p)*44 + jl)*25 + h6 + d]   = a0 * i0v;
            attn_s[((2*p+1)*44 + jl)*25 + h6 + d] = a1 * i1v;
        }
    }
    for (int idx = tid; idx < CC*NOUT; idx += NTA) ws[idx] = W[idx];
    for (int idx = tid; idx < NOUT; idx += NTA) bs[idx] = bvec[idx];
    __syncthreads();

    const int NP = (MODE == 0) ? 3 : 1;      // passes of 6 output channels
    float res[3][TQ][6];                     // MODE1 uses res[0] only
    #pragma unroll
    for (int pass = 0; pass < NP; ++pass) {
        int cf0 = h * (NOUT/4) + pass*6;
        float acc[TQ][6];
        #pragma unroll
        for (int t = 0; t < TQ; ++t)
            #pragma unroll
            for (int ci = 0; ci < 6; ++ci) acc[t][ci] = bs[cf0 + ci];
        #pragma unroll
        for (int u = 0; u < CC; ++u) {
            float wv[6], av[TQ];
            #pragma unroll
            for (int ci = 0; ci < 6; ++ci) wv[ci] = ws[u*NOUT + cf0 + ci];
            #pragma unroll
            for (int t = 0; t < TQ; ++t) av[t] = attn_s[(t*44 + jl)*25 + u];
            #pragma unroll
            for (int t = 0; t < TQ; ++t)
                #pragma unroll
                for (int ci = 0; ci < 6; ++ci) acc[t][ci] = fmaf(av[t], wv[ci], acc[t][ci]);
        }
        if (MODE == 0) {
            int which = cf0 / CC, chb = cf0 % CC;
            float* dst = (which == 0) ? g_q2 : (which == 1) ? g_k2 : g_v2;
            #pragma unroll
            for (int t = 0; t < TQ; ++t)
                #pragma unroll
                for (int ci = 0; ci < 6; ++ci)
                    dst[((size_t)(b*HT + i0 + t) * CC + chb + ci) * WD + j] = acc[t][ci];
        } else {
            #pragma unroll
            for (int t = 0; t < TQ; ++t)
                #pragma unroll
                for (int ci = 0; ci < 6; ++ci) res[0][t][ci] = acc[t][ci];
        }
    }

    if (MODE == 1) {
        // stage to smem, then fully coalesced stores
        __syncthreads();
        float* res_s = smem;                 // [264][25]
        int cf0 = h * 6;
        #pragma unroll
        for (int t = 0; t < TQ; ++t)
            #pragma unroll
            for (int ci = 0; ci < 6; ++ci)
                res_s[(t*44 + jl)*25 + cf0 + ci] = res[0][t][ci];
        __syncthreads();
        #pragma unroll
        for (int t = 0; t < TQ; ++t) {
            float* ob = outp + ((size_t)(b*HT + i0 + t) * WD + jb) * CC;
            for (int o = tid; o < 44*CC; o += NTA) {
                int px = o / CC, c = o - px*CC;
                ob[o] = res_s[(t*44 + px)*25 + c];
            }
        }
    }
}

// ---------------------------------------------------------------------------
extern "C" void kernel_launch(void* const* d_in, const int* in_sizes, int n_in,
                              void* d_out, int out_size) {
    (void)in_sizes; (void)n_in; (void)out_size;
    const float* x      = (const float*)d_in[0];
    const float* W_lin  = (const float*)d_in[1];
    const float* b_lin  = (const float*)d_in[2];
    const float* W_qkv  = (const float*)d_in[3];
    const float* b_qkv  = (const float*)d_in[4];
    const float* rpb    = (const float*)d_in[5];
    const float* W_proj = (const float*)d_in[6];
    const float* b_proj = (const float*)d_in[7];
    float* out = (float*)d_out;

    float *q, *k, *v, *q2, *k2, *v2, *wc, *bc;
    cudaGetSymbolAddress((void**)&q,  g_q);
    cudaGetSymbolAddress((void**)&k,  g_k);
    cudaGetSymbolAddress((void**)&v,  g_v);
    cudaGetSymbolAddress((void**)&q2, g_q2);
    cudaGetSymbolAddress((void**)&k2, g_k2);
    cudaGetSymbolAddress((void**)&v2, g_v2);
    cudaGetSymbolAddress((void**)&wc, g_wc);
    cudaGetSymbolAddress((void**)&bc, g_bc);

    k_comb<<<7, 256>>>(W_proj, b_proj, W_qkv, b_qkv);
    k_linqkv<<<BB*HT*2, 352>>>(x, W_lin, b_lin, W_qkv, b_qkv);
    k_attn<0><<<128, NTA>>>(q,  k,  v,  rpb, wc,     bc,     nullptr);
    k_attn<1><<<128, NTA>>>(q2, k2, v2, rpb, W_proj, b_proj, out);
}

// round 5
// speedup vs baseline: 1.3190x; 1.3190x over previous
#include <cuda_runtime.h>

// 0: x [2,192,88,133] f32, 1: W_lin [133,24], 2: b_lin [24], 3: W_qkv [24,72],
// 4: b_qkv [72], 5: rpb [4,49,49], 6: W_proj [24,24], 7: b_proj [24]
// output: [2,192,88,24] f32

#define BB   2
#define HT   192
#define WD   88
#define FIN  133
#define CC   24
#define NH   4
#define DH   6
#define WIN  25
#define NPIX (BB*HT*WD)   // 33792
#define RPBW 49
#define TR   3            // query rows per attn block
#define NT   352          // attn threads: 88 cols x 4 heads
#define BROWS 29
#define BH   (BROWS*RPBW) // 1421

typedef unsigned long long ull;

// Scratch (device globals: allocation-free)
__device__ float g_q[NPIX*CC], g_k[NPIX*CC], g_v[NPIX*CC];     // layer-1 qkv [bi][ch][col]
__device__ float g_q2[NPIX*CC], g_k2[NPIX*CC], g_v2[NPIX*CC];  // layer-2 qkv
__device__ float g_wc[CC*72], g_bc[72];                        // proj@qkv combined

// ---- packed f32x2 helpers --------------------------------------------------
__device__ __forceinline__ ull pk2(float lo, float hi) {
    ull r; asm("mov.b64 %0, {%1,%2};" : "=l"(r) : "f"(lo), "f"(hi)); return r;
}
__device__ __forceinline__ ull bc2(float v) { return pk2(v, v); }
__device__ __forceinline__ void upk2(float& lo, float& hi, ull v) {
    asm("mov.b64 {%0,%1}, %2;" : "=f"(lo), "=f"(hi) : "l"(v));
}
__device__ __forceinline__ ull fma2(ull a, ull b, ull c) {
    ull d; asm("fma.rn.f32x2 %0, %1, %2, %3;" : "=l"(d) : "l"(a), "l"(b), "l"(c)); return d;
}
__device__ __forceinline__ ull add2(ull a, ull b) {
    ull d; asm("add.rn.f32x2 %0, %1, %2;" : "=l"(d) : "l"(a), "l"(b)); return d;
}

// ---------------------------------------------------------------------------
// Setup: Wcomb = W_proj @ W_qkv, bcomb = b_proj @ W_qkv + b_qkv (q-cols scaled)
// ---------------------------------------------------------------------------
__global__ void k_comb(const float* __restrict__ Wp, const float* __restrict__ bp,
                       const float* __restrict__ Wq, const float* __restrict__ bq) {
    int t = blockIdx.x * blockDim.x + threadIdx.x;
    const float QS = 0.40824829046386302f;
    if (t < CC*72) {
        int u = t / 72, cf = t % 72;
        float a = 0.f;
        #pragma unroll
        for (int w = 0; w < CC; ++w) a = fmaf(Wp[u*CC + w], Wq[w*72 + cf], a);
        if (cf < CC) a *= QS;
        g_wc[t] = a;
    }
    if (t < 72) {
        float a = bq[t];
        #pragma unroll
        for (int w = 0; w < CC; ++w) a = fmaf(bp[w], Wq[w*72 + t], a);
        if (t < CC) a *= QS;
        g_bc[t] = a;
    }
}

// ---------------------------------------------------------------------------
// Fused linear+ReLU+qkv: block = 44-pixel half row. Writes g_q/g_k/g_v d-major.
// ---------------------------------------------------------------------------
__global__ void __launch_bounds__(352) k_linqkv(const float* __restrict__ x,
                                                const float* __restrict__ Wl,
                                                const float* __restrict__ bl,
                                                const float* __restrict__ Wq,
                                                const float* __restrict__ bq) {
    __shared__ float sm[11872];
    float* xs = sm;               // 44*133 = 5852
    float* wl = sm + 5852;        // 133*24 = 3192
    float* hs = sm + 9044;        // 44*25  = 1100
    float* wq = sm + 10144;       // 24*72  = 1728

    int blk = blockIdx.x;
    int bi = blk >> 1, jb = (blk & 1) * 44;
    int tid = threadIdx.x;

    const float* xb = x + ((size_t)bi * WD + jb) * FIN;
    for (int idx = tid; idx < 44*FIN; idx += 352) xs[idx] = xb[idx];
    for (int idx = tid; idx < FIN*CC; idx += 352) wl[idx] = Wl[idx];
    for (int idx = tid; idx < CC*72; idx += 352) wq[idx] = Wq[idx];
    __syncthreads();

    int jl = tid % 44, cg = tid / 44;      // cg in [0,8): 3 channels each
    int c0 = cg * 3;
    float acc[3];
    #pragma unroll
    for (int i = 0; i < 3; ++i) acc[i] = bl[c0 + i];
    #pragma unroll 7
    for (int f = 0; f < FIN; ++f) {
        float xf = xs[jl*FIN + f];
        #pragma unroll
        for (int i = 0; i < 3; ++i) acc[i] = fmaf(xf, wl[f*CC + c0 + i], acc[i]);
    }
    #pragma unroll
    for (int i = 0; i < 3; ++i) hs[jl*25 + c0 + i] = fmaxf(acc[i], 0.f);
    __syncthreads();

    for (int o = tid; o < 44*72; o += 352) {
        int cf = o / 44, j2 = o - cf*44;
        float a = bq[cf];
        #pragma unroll
        for (int u = 0; u < CC; ++u) a = fmaf(hs[j2*25 + u], wq[u*72 + cf], a);
        if (cf < CC) a *= 0.40824829046386302f;
        int which = cf / CC, ch = cf % CC;
        float* dst = (which == 0) ? g_q : (which == 1) ? g_k : g_v;
        dst[((size_t)bi * CC + ch) * WD + jb + j2] = a;
    }
}

// ---------------------------------------------------------------------------
// Attention (TR=3, 352 thr): queries (t0,t1) packed f32x2, t2 scalar.
// Direct exp w/ center-score subtraction; -60 shift kills out-of-window rows.
// MODE 0: epilogue -> layer-2 qkv via Wcomb. MODE 1: final projection.
// ---------------------------------------------------------------------------
template<int MODE>
__global__ void __launch_bounds__(NT, 1) k_attn(
    const float* __restrict__ Q, const float* __restrict__ K,
    const float* __restrict__ V, const float* __restrict__ rpb,
    const float* __restrict__ W, const float* __restrict__ bvec,
    float* __restrict__ outp)
{
    __shared__ float smem[9908];
    float* bias_s = smem;           // 4*29*49 = 5684
    float* k_s = smem + 5684;       // 2112
    float* v_s = smem + 7796;       // 2112

    int blk = blockIdx.x;           // 128 blocks
    int b = blk >> 6, it = blk & 63;
    int i0 = it * TR;
    int tid = threadIdx.x;
    int j = tid % WD, h = tid / WD, h6 = h * DH;

    int sii[TR];
    #pragma unroll
    for (int t = 0; t < TR; ++t) sii[t] = min(max(i0 + t - 12, 0), HT - WIN);
    int r_lo = sii[0];
    int nrows = sii[2] + WIN - r_lo;           // 25..27
    int row_base = r_lo - i0 + 22;

    int sjj = min(max(j - 12, 0), WD - WIN);
    int bjcol = sjj - j + 24;

    for (int idx = tid; idx < NH*BH; idx += NT) {
        int hh = idx / BH, rem = idx - hh*BH;
        int rr = rem / RPBW, c = rem - rr*RPBW;
        int src = min(max(row_base + rr, 0), RPBW - 1);
        bias_s[idx] = rpb[hh*RPBW*RPBW + src*RPBW + c];
    }

    // q vectors + negated center scores
    float qv[TR][DH], nsc[TR];
    #pragma unroll
    for (int t = 0; t < TR; ++t) {
        const float* qb = Q + ((size_t)(b*HT + i0 + t) * CC + h6) * WD + j;
        const float* kc = K + ((size_t)(b*HT + i0 + t) * CC + h6) * WD + j;
        float s = 0.f;
        #pragma unroll
        for (int d = 0; d < DH; ++d) {
            qv[t][d] = qb[d*WD];
            s = fmaf(qv[t][d], kc[d*WD], s);
        }
        nsc[t] = -s;
    }
    ull qvp[DH];
    #pragma unroll
    for (int d = 0; d < DH; ++d) qvp[d] = pk2(qv[0][d], qv[1][d]);

    ull accp[DH], lp = 0ULL;
    float acc2[DH], l2 = 0.f;
    #pragma unroll
    for (int d = 0; d < DH; ++d) { accp[d] = 0ULL; acc2[d] = 0.f; }

    // register prefetch of first K/V row
    float kr[6], vr[6];
    {
        size_t off = (size_t)(b*HT + r_lo) * CC * WD;
        #pragma unroll
        for (int u = 0; u < 6; ++u) {
            kr[u] = g_k == nullptr ? 0.f : 0.f;  // (dead; appease nothing)
        }
        #pragma unroll
        for (int u = 0; u < 6; ++u) {
            kr[u] = K[off + tid + u*NT];
            vr[u] = V[off + tid + u*NT];
        }
    }

    for (int rr = 0; rr < nrows; ++rr) {
        int r = r_lo + rr;
        __syncthreads();
        #pragma unroll
        for (int u = 0; u < 6; ++u) {
            k_s[tid + u*NT] = kr[u];
            v_s[tid + u*NT] = vr[u];
        }
        __syncthreads();
        if (rr + 1 < nrows) {
            size_t off = (size_t)(b*HT + r + 1) * CC * WD;
            #pragma unroll
            for (int u = 0; u < 6; ++u) {
                kr[u] = K[off + tid + u*NT];
                vr[u] = V[off + tid + u*NT];
            }
        }

        float sh0 = nsc[0] + ((r <= sii[0] + 24) ? 0.f : -60.f);
        float sh1 = nsc[1] + ((r >= sii[1] && r <= sii[1] + 24) ? 0.f : -60.f);
        float sh2 = nsc[2] + ((r >= sii[2]) ? 0.f : -60.f);
        ull nscp = pk2(sh0, sh1);

        const float* kb = k_s + h6*WD + sjj;
        const float* vb = v_s + h6*WD + sjj;
        const float* brow = bias_s + h*BH + rr*RPBW + bjcol;
        const float* br0 = brow + 2*RPBW;
        const float* br1 = brow + RPBW;
        const float* br2 = brow;

        #pragma unroll 5
        for (int c = 0; c < WIN; ++c) {
            float kc[DH], vc[DH];
            #pragma unroll
            for (int d = 0; d < DH; ++d) { kc[d] = kb[d*WD + c]; vc[d] = vb[d*WD + c]; }

            // packed pair (t0, t1)
            ull s = add2(pk2(br0[c], br1[c]), nscp);
            #pragma unroll
            for (int d = 0; d < DH; ++d) s = fma2(qvp[d], bc2(kc[d]), s);
            float s0, s1; upk2(s0, s1, s);
            ull pp = pk2(__expf(s0), __expf(s1));
            lp = add2(lp, pp);
            #pragma unroll
            for (int d = 0; d < DH; ++d) accp[d] = fma2(pp, bc2(vc[d]), accp[d]);

            // scalar t2
            float s2 = br2[c] + sh2;
            #pragma unroll
            for (int d = 0; d < DH; ++d) s2 = fmaf(qv[2][d], kc[d], s2);
            float p2 = __expf(s2);
            l2 += p2;
            #pragma unroll
            for (int d = 0; d < DH; ++d) acc2[d] = fmaf(p2, vc[d], acc2[d]);
        }
    }

    // ---- epilogue ----------------------------------------------------------
    __syncthreads();
    float* attn_s = smem;                    // [3][88][25] = 6600
    const int NOUT = (MODE == 0) ? 72 : 24;
    float* ws = smem + 6600;                 // <=1728
    float* bs = smem + 8328;                 // <=72
    {
        float l0, l1; upk2(l0, l1, lp);
        float i0v = __fdividef(1.f, l0);
        float i1v = __fdividef(1.f, l1);
        float i2v = __fdividef(1.f, l2);
        #pragma unroll
        for (int d = 0; d < DH; ++d) {
            float a0, a1; upk2(a0, a1, accp[d]);
            attn_s[(0*WD + j)*25 + h6 + d] = a0 * i0v;
            attn_s[(1*WD + j)*25 + h6 + d] = a1 * i1v;
            attn_s[(2*WD + j)*25 + h6 + d] = acc2[d] * i2v;
        }
    }
    for (int idx = tid; idx < CC*NOUT; idx += NT) ws[idx] = W[idx];
    for (int idx = tid; idx < NOUT; idx += NT) bs[idx] = bvec[idx];
    __syncthreads();

    if (MODE == 0) {
        #pragma unroll
        for (int pass = 0; pass < 3; ++pass) {
            int cf0 = h * 18 + pass * 6;
            float acc[TR][6];
            #pragma unroll
            for (int t = 0; t < TR; ++t)
                #pragma unroll
                for (int ci = 0; ci < 6; ++ci) acc[t][ci] = bs[cf0 + ci];
            #pragma unroll
            for (int u = 0; u < CC; ++u) {
                float wv[6], av[TR];
                #pragma unroll
                for (int ci = 0; ci < 6; ++ci) wv[ci] = ws[u*72 + cf0 + ci];
                #pragma unroll
                for (int t = 0; t < TR; ++t) av[t] = attn_s[(t*WD + j)*25 + u];
                #pragma unroll
                for (int t = 0; t < TR; ++t)
                    #pragma unroll
                    for (int ci = 0; ci < 6; ++ci)
                        acc[t][ci] = fmaf(av[t], wv[ci], acc[t][ci]);
            }
            int which = (cf0 >= 48) ? 2 : (cf0 >= 24 ? 1 : 0);
            int chb = cf0 - which * CC;
            float* dst = (which == 0) ? g_q2 : (which == 1) ? g_k2 : g_v2;
            #pragma unroll
            for (int t = 0; t < TR; ++t)
                #pragma unroll
                for (int ci = 0; ci < 6; ++ci)
                    dst[((size_t)(b*HT + i0 + t) * CC + chb + ci) * WD + j] = acc[t][ci];
        }
    } else {
        int cf0 = h * 6;
        float acc[TR][6];
        #pragma unroll
        for (int t = 0; t < TR; ++t)
            #pragma unroll
            for (int ci = 0; ci < 6; ++ci) acc[t][ci] = bs[cf0 + ci];
        #pragma unroll
        for (int u = 0; u < CC; ++u) {
            float wv[6], av[TR];
            #pragma unroll
            for (int ci = 0; ci < 6; ++ci) wv[ci] = ws[u*24 + cf0 + ci];
            #pragma unroll
            for (int t = 0; t < TR; ++t) av[t] = attn_s[(t*WD + j)*25 + u];
            #pragma unroll
            for (int t = 0; t < TR; ++t)
                #pragma unroll
                for (int ci = 0; ci < 6; ++ci)
                    acc[t][ci] = fmaf(av[t], wv[ci], acc[t][ci]);
        }
        __syncthreads();
        float* res_s = smem;                 // [3][88][24] = 6336
        #pragma unroll
        for (int t = 0; t < TR; ++t)
            #pragma unroll
            for (int ci = 0; ci < 6; ++ci)
                res_s[(t*WD + j)*CC + cf0 + ci] = acc[t][ci];
        __syncthreads();
        float* ob = outp + (size_t)(b*HT + i0) * WD * CC;
        for (int o = tid; o < TR*WD*CC; o += NT) ob[o] = res_s[o];
    }
}

// ---------------------------------------------------------------------------
extern "C" void kernel_launch(void* const* d_in, const int* in_sizes, int n_in,
                              void* d_out, int out_size) {
    (void)in_sizes; (void)n_in; (void)out_size;
    const float* x      = (const float*)d_in[0];
    const float* W_lin  = (const float*)d_in[1];
    const float* b_lin  = (const float*)d_in[2];
    const float* W_qkv  = (const float*)d_in[3];
    const float* b_qkv  = (const float*)d_in[4];
    const float* rpb    = (const float*)d_in[5];
    const float* W_proj = (const float*)d_in[6];
    const float* b_proj = (const float*)d_in[7];
    float* out = (float*)d_out;

    float *q, *k, *v, *q2, *k2, *v2, *wc, *bc;
    cudaGetSymbolAddress((void**)&q,  g_q);
    cudaGetSymbolAddress((void**)&k,  g_k);
    cudaGetSymbolAddress((void**)&v,  g_v);
    cudaGetSymbolAddress((void**)&q2, g_q2);
    cudaGetSymbolAddress((void**)&k2, g_k2);
    cudaGetSymbolAddress((void**)&v2, g_v2);
    cudaGetSymbolAddress((void**)&wc, g_wc);
    cudaGetSymbolAddress((void**)&bc, g_bc);

    k_comb<<<7, 256>>>(W_proj, b_proj, W_qkv, b_qkv);
    k_linqkv<<<BB*HT*2, 352>>>(x, W_lin, b_lin, W_qkv, b_qkv);
    k_attn<0><<<128, NT>>>(q,  k,  v,  rpb, wc,     bc,     nullptr);
    k_attn<1><<<128, NT>>>(q2, k2, v2, rpb, W_proj, b_proj, out);
}

// round 6
// speedup vs baseline: 1.3917x; 1.0551x over previous
#include <cuda_runtime.h>

// 0: x [2,192,88,133] f32, 1: W_lin [133,24], 2: b_lin [24], 3: W_qkv [24,72],
// 4: b_qkv [72], 5: rpb [4,49,49], 6: W_proj [24,24], 7: b_proj [24]
// output: [2,192,88,24] f32

#define BB   2
#define HT   192
#define WD   88
#define FIN  133
#define CC   24
#define NH   4
#define DH   6
#define WIN  25
#define NPIX (BB*HT*WD)   // 33792
#define RPBW 49
#define TR   3            // query rows per attn block
#define NT   352          // attn threads: 88 cols x 4 heads
#define BROWS 29
#define BH   (BROWS*RPBW) // 1421
#define LOG2E 1.4426950408889634f

typedef unsigned long long ull;

// Scratch (device globals: allocation-free)
__device__ float g_q[NPIX*CC], g_k[NPIX*CC], g_v[NPIX*CC];     // layer-1 qkv [bi][ch][col]
__device__ float g_q2[NPIX*CC], g_k2[NPIX*CC], g_v2[NPIX*CC];  // layer-2 qkv
__device__ float g_wc[CC*72], g_bc[72];                        // proj@qkv combined

// ---- packed f32x2 helpers --------------------------------------------------
__device__ __forceinline__ ull pk2(float lo, float hi) {
    ull r; asm("mov.b64 %0, {%1,%2};" : "=l"(r) : "f"(lo), "f"(hi)); return r;
}
__device__ __forceinline__ ull bc2(float v) { return pk2(v, v); }
__device__ __forceinline__ void upk2(float& lo, float& hi, ull v) {
    asm("mov.b64 {%0,%1}, %2;" : "=f"(lo), "=f"(hi) : "l"(v));
}
__device__ __forceinline__ ull fma2(ull a, ull b, ull c) {
    ull d; asm("fma.rn.f32x2 %0, %1, %2, %3;" : "=l"(d) : "l"(a), "l"(b), "l"(c)); return d;
}
__device__ __forceinline__ ull add2(ull a, ull b) {
    ull d; asm("add.rn.f32x2 %0, %1, %2;" : "=l"(d) : "l"(a), "l"(b)); return d;
}
__device__ __forceinline__ ull mul2(ull a, ull b) {
    ull d; asm("mul.rn.f32x2 %0, %1, %2;" : "=l"(d) : "l"(a), "l"(b)); return d;
}
__device__ __forceinline__ float ex2f(float x) {
    float y; asm("ex2.approx.f32 %0, %1;" : "=f"(y) : "f"(x)); return y;
}
__device__ __forceinline__ ull lds64(const float* p) {
    return *reinterpret_cast<const ull*>(p);   // 8B-aligned by construction
}

// ---------------------------------------------------------------------------
// Setup: Wcomb = W_proj @ W_qkv, bcomb = b_proj @ W_qkv + b_qkv
// (q columns scaled by dh^-0.5 * log2(e) so attention can use ex2 directly)
// ---------------------------------------------------------------------------
__global__ void k_comb(const float* __restrict__ Wp, const float* __restrict__ bp,
                       const float* __restrict__ Wq, const float* __restrict__ bq) {
    int t = blockIdx.x * blockDim.x + threadIdx.x;
    const float QS = 0.40824829046386302f * LOG2E;
    if (t < CC*72) {
        int u = t / 72, cf = t % 72;
        float a = 0.f;
        #pragma unroll
        for (int w = 0; w < CC; ++w) a = fmaf(Wp[u*CC + w], Wq[w*72 + cf], a);
        if (cf < CC) a *= QS;
        g_wc[t] = a;
    }
    if (t < 72) {
        float a = bq[t];
        #pragma unroll
        for (int w = 0; w < CC; ++w) a = fmaf(bp[w], Wq[w*72 + t], a);
        if (t < CC) a *= QS;
        g_bc[t] = a;
    }
}

// ---------------------------------------------------------------------------
// Fused linear+ReLU+qkv: block = 44-pixel half row. Writes g_q/g_k/g_v d-major.
// ---------------------------------------------------------------------------
__global__ void __launch_bounds__(352) k_linqkv(const float* __restrict__ x,
                                                const float* __restrict__ Wl,
                                                const float* __restrict__ bl,
                                                const float* __restrict__ Wq,
                                                const float* __restrict__ bq) {
    __shared__ float sm[11872];
    float* xs = sm;               // 44*133 = 5852
    float* wl = sm + 5852;        // 133*24 = 3192
    float* hs = sm + 9044;        // 44*25  = 1100
    float* wq = sm + 10144;       // 24*72  = 1728

    int blk = blockIdx.x;
    int bi = blk >> 1, jb = (blk & 1) * 44;
    int tid = threadIdx.x;

    const float* xb = x + ((size_t)bi * WD + jb) * FIN;
    for (int idx = tid; idx < 44*FIN; idx += 352) xs[idx] = xb[idx];
    for (int idx = tid; idx < FIN*CC; idx += 352) wl[idx] = Wl[idx];
    for (int idx = tid; idx < CC*72; idx += 352) wq[idx] = Wq[idx];
    __syncthreads();

    int jl = tid % 44, cg = tid / 44;      // cg in [0,8): 3 channels each
    int c0 = cg * 3;
    float acc[3];
    #pragma unroll
    for (int i = 0; i < 3; ++i) acc[i] = bl[c0 + i];
    #pragma unroll 7
    for (int f = 0; f < FIN; ++f) {
        float xf = xs[jl*FIN + f];
        #pragma unroll
        for (int i = 0; i < 3; ++i) acc[i] = fmaf(xf, wl[f*CC + c0 + i], acc[i]);
    }
    #pragma unroll
    for (int i = 0; i < 3; ++i) hs[jl*25 + c0 + i] = fmaxf(acc[i], 0.f);
    __syncthreads();

    const float QS = 0.40824829046386302f * LOG2E;
    for (int o = tid; o < 44*72; o += 352) {
        int cf = o / 44, j2 = o - cf*44;
        float a = bq[cf];
        #pragma unroll
        for (int u = 0; u < CC; ++u) a = fmaf(hs[j2*25 + u], wq[u*72 + cf], a);
        if (cf < CC) a *= QS;
        int which = cf / CC, ch = cf % CC;
        float* dst = (which == 0) ? g_q : (which == 1) ? g_k : g_v;
        dst[((size_t)bi * CC + ch) * WD + jb + j2] = a;
    }
}

// ---------------------------------------------------------------------------
// Attention (TR=3, 352 thr): f32x2 packed over COLUMN pairs; K/V via LDS.64
// straight into fma2 operands (no broadcast movs). Scores in log2 units ->
// raw ex2.approx. Window aligned to even smem col; edge lane masked by mul2.
// MODE 0: epilogue -> layer-2 qkv via Wcomb. MODE 1: final projection.
// ---------------------------------------------------------------------------
template<int MODE>
__global__ void __launch_bounds__(NT, 1) k_attn(
    const float* __restrict__ Q, const float* __restrict__ K,
    const float* __restrict__ V, const float* __restrict__ rpb,
    const float* __restrict__ W, const float* __restrict__ bvec,
    float* __restrict__ outp)
{
    __shared__ float smem[9908];
    float* bias_s = smem;           // 4*29*49 = 5684 (scaled by log2e)
    float* k_s = smem + 5684;       // 24*88 = 2112
    float* v_s = smem + 7796;       // 2112

    int blk = blockIdx.x;           // 128 blocks
    int b = blk >> 6, it = blk & 63;
    int i0 = it * TR;
    int tid = threadIdx.x;
    int j = tid % WD, h = tid / WD, h6 = h * DH;

    int sii[TR];
    #pragma unroll
    for (int t = 0; t < TR; ++t) sii[t] = min(max(i0 + t - 12, 0), HT - WIN);
    int r_lo = sii[0];
    int nrows = sii[2] + WIN - r_lo;           // 25..27
    int row_base = r_lo - i0 + 22;

    int sjj = min(max(j - 12, 0), WD - WIN);
    int e0 = sjj & 1;
    int c0 = sjj - e0;                          // even-aligned window start
    int cb = c0 + 24 - j;                       // bias column base

    for (int idx = tid; idx < NH*BH; idx += NT) {
        int hh = idx / BH, rem = idx - hh*BH;
        int rr = rem / RPBW, c = rem - rr*RPBW;
        int src = min(max(row_base + rr, 0), RPBW - 1);
        bias_s[idx] = rpb[hh*RPBW*RPBW + src*RPBW + c] * LOG2E;
    }

    // q vectors (broadcast-packed) + negated center scores (log2 units)
    float nsc[TR];
    ull qb2[TR][DH];
    #pragma unroll
    for (int t = 0; t < TR; ++t) {
        const float* qb = Q + ((size_t)(b*HT + i0 + t) * CC + h6) * WD + j;
        const float* kc = K + ((size_t)(b*HT + i0 + t) * CC + h6) * WD + j;
        float s = 0.f;
        #pragma unroll
        for (int d = 0; d < DH; ++d) {
            float qd = qb[d*WD];
            s = fmaf(qd, kc[d*WD], s);
            qb2[t][d] = bc2(qd);
        }
        nsc[t] = -s;
    }

    // edge masks (block-constant)
    ull mfirst = pk2(e0 ? 0.f : 1.f, 1.f);
    ull mlast  = pk2(1.f, e0 ? 1.f : 0.f);

    ull accp[TR][DH], lp[TR];
    #pragma unroll
    for (int t = 0; t < TR; ++t) {
        lp[t] = 0ULL;
        #pragma unroll
        for (int d = 0; d < DH; ++d) accp[t][d] = 0ULL;
    }

    // register prefetch of first K/V row
    float kr[6], vr[6];
    {
        size_t off = (size_t)(b*HT + r_lo) * CC * WD;
        #pragma unroll
        for (int u = 0; u < 6; ++u) {
            kr[u] = K[off + tid + u*NT];
            vr[u] = V[off + tid + u*NT];
        }
    }

    for (int rr = 0; rr < nrows; ++rr) {
        int r = r_lo + rr;
        __syncthreads();
        #pragma unroll
        for (int u = 0; u < 6; ++u) {
            k_s[tid + u*NT] = kr[u];
            v_s[tid + u*NT] = vr[u];
        }
        __syncthreads();
        if (rr + 1 < nrows) {
            size_t off = (size_t)(b*HT + r + 1) * CC * WD;
            #pragma unroll
            for (int u = 0; u < 6; ++u) {
                kr[u] = K[off + tid + u*NT];
                vr[u] = V[off + tid + u*NT];
            }
        }

        // per-row shifts (include row-validity kill, log2 units)
        ull shp[TR];
        shp[0] = bc2(nsc[0] + ((r <= sii[0] + 24) ? 0.f : -87.f));
        shp[1] = bc2(nsc[1] + ((r >= sii[1] && r <= sii[1] + 24) ? 0.f : -87.f));
        shp[2] = bc2(nsc[2] + ((r >= sii[2]) ? 0.f : -87.f));

        const float* kb = k_s + h6*WD + c0;
        const float* vb = v_s + h6*WD + c0;
        const float* br0 = bias_s + h*BH + (rr + 2)*RPBW + cb;  // query 0
        const float* br1 = br0 - RPBW;
        const float* br2 = br1 - RPBW;

        #pragma unroll
        for (int p = 0; p < 13; ++p) {
            ull kpair[DH], vpair[DH];
            #pragma unroll
            for (int d = 0; d < DH; ++d) {
                kpair[d] = lds64(kb + d*WD + 2*p);
                vpair[d] = lds64(vb + d*WD + 2*p);
            }
            #pragma unroll
            for (int t = 0; t < TR; ++t) {
                const float* br = (t == 0) ? br0 : (t == 1) ? br1 : br2;
                ull s = add2(pk2(br[2*p], br[2*p + 1]), shp[t]);
                #pragma unroll
                for (int d = 0; d < DH; ++d) s = fma2(qb2[t][d], kpair[d], s);
                float s0, s1; upk2(s0, s1, s);
                ull pp = pk2(ex2f(s0), ex2f(s1));
                if (p == 0)  pp = mul2(pp, mfirst);
                if (p == 12) pp = mul2(pp, mlast);
                lp[t] = add2(lp[t], pp);
                #pragma unroll
                for (int d = 0; d < DH; ++d) accp[t][d] = fma2(pp, vpair[d], accp[t][d]);
            }
        }
    }

    // ---- epilogue ----------------------------------------------------------
    __syncthreads();
    float* attn_s = smem;                    // [3][88][25] = 6600
    const int NOUT = (MODE == 0) ? 72 : 24;
    float* ws = smem + 6600;                 // <=1728
    float* bs = smem + 8328;                 // <=72
    #pragma unroll
    for (int t = 0; t < TR; ++t) {
        float l0, l1; upk2(l0, l1, lp[t]);
        float inv = __fdividef(1.f, l0 + l1);
        #pragma unroll
        for (int d = 0; d < DH; ++d) {
            float a0, a1; upk2(a0, a1, accp[t][d]);
            attn_s[(t*WD + j)*25 + h6 + d] = (a0 + a1) * inv;
        }
    }
    for (int idx = tid; idx < CC*NOUT; idx += NT) ws[idx] = W[idx];
    for (int idx = tid; idx < NOUT; idx += NT) bs[idx] = bvec[idx];
    __syncthreads();

    if (MODE == 0) {
        #pragma unroll
        for (int pass = 0; pass < 3; ++pass) {
            int cf0 = h * 18 + pass * 6;
            float acc[TR][6];
            #pragma unroll
            for (int t = 0; t < TR; ++t)
                #pragma unroll
                for (int ci = 0; ci < 6; ++ci) acc[t][ci] = bs[cf0 + ci];
            #pragma unroll
            for (int u = 0; u < CC; ++u) {
                float wv[6], av[TR];
                #pragma unroll
                for (int ci = 0; ci < 6; ++ci) wv[ci] = ws[u*72 + cf0 + ci];
                #pragma unroll
                for (int t = 0; t < TR; ++t) av[t] = attn_s[(t*WD + j)*25 + u];
                #pragma unroll
                for (int t = 0; t < TR; ++t)
                    #pragma unroll
                    for (int ci = 0; ci < 6; ++ci)
                        acc[t][ci] = fmaf(av[t], wv[ci], acc[t][ci]);
            }
            int which = (cf0 >= 48) ? 2 : (cf0 >= 24 ? 1 : 0);
            int chb = cf0 - which * CC;
            float* dst = (which == 0) ? g_q2 : (which == 1) ? g_k2 : g_v2;
            #pragma unroll
            for (int t = 0; t < TR; ++t)
                #pragma unroll
                for (int ci = 0; ci < 6; ++ci)
                    dst[((size_t)(b*HT + i0 + t) * CC + chb + ci) * WD + j] = acc[t][ci];
        }
    } else {
        int cf0 = h * 6;
        float acc[TR][6];
        #pragma unroll
        for (int t = 0; t < TR; ++t)
            #pragma unroll
            for (int ci = 0; ci < 6; ++ci) acc[t][ci] = bs[cf0 + ci];
        #pragma unroll
        for (int u = 0; u < CC; ++u) {
            float wv[6], av[TR];
            #pragma unroll
            for (int ci = 0; ci < 6; ++ci) wv[ci] = ws[u*24 + cf0 + ci];
            #pragma unroll
            for (int t = 0; t < TR; ++t) av[t] = attn_s[(t*WD + j)*25 + u];
            #pragma unroll
            for (int t = 0; t < TR; ++t)
                #pragma unroll
                for (int ci = 0; ci < 6; ++ci)
                    acc[t][ci] = fmaf(av[t], wv[ci], acc[t][ci]);
        }
        __syncthreads();
        float* res_s = smem;                 // [3][88][24] = 6336
        #pragma unroll
        for (int t = 0; t < TR; ++t)
            #pragma unroll
            for (int ci = 0; ci < 6; ++ci)
                res_s[(t*WD + j)*CC + cf0 + ci] = acc[t][ci];
        __syncthreads();
        float* ob = outp + (size_t)(b*HT + i0) * WD * CC;
        for (int o = tid; o < TR*WD*CC; o += NT) ob[o] = res_s[o];
    }
}

// ---------------------------------------------------------------------------
extern "C" void kernel_launch(void* const* d_in, const int* in_sizes, int n_in,
                              void* d_out, int out_size) {
    (void)in_sizes; (void)n_in; (void)out_size;
    const float* x      = (const float*)d_in[0];
    const float* W_lin  = (const float*)d_in[1];
    const float* b_lin  = (const float*)d_in[2];
    const float* W_qkv  = (const float*)d_in[3];
    const float* b_qkv  = (const float*)d_in[4];
    const float* rpb    = (const float*)d_in[5];
    const float* W_proj = (const float*)d_in[6];
    const float* b_proj = (const float*)d_in[7];
    float* out = (float*)d_out;

    float *q, *k, *v, *q2, *k2, *v2, *wc, *bc;
    cudaGetSymbolAddress((void**)&q,  g_q);
    cudaGetSymbolAddress((void**)&k,  g_k);
    cudaGetSymbolAddress((void**)&v,  g_v);
    cudaGetSymbolAddress((void**)&q2, g_q2);
    cudaGetSymbolAddress((void**)&k2, g_k2);
    cudaGetSymbolAddress((void**)&v2, g_v2);
    cudaGetSymbolAddress((void**)&wc, g_wc);
    cudaGetSymbolAddress((void**)&bc, g_bc);

    k_comb<<<7, 256>>>(W_proj, b_proj, W_qkv, b_qkv);
    k_linqkv<<<BB*HT*2, 352>>>(x, W_lin, b_lin, W_qkv, b_qkv);
    k_attn<0><<<128, NT>>>(q,  k,  v,  rpb, wc,     bc,     nullptr);
    k_attn<1><<<128, NT>>>(q2, k2, v2, rpb, W_proj, b_proj, out);
}